// round 1
// baseline (speedup 1.0000x reference)
#include <cuda_runtime.h>
#include <cstdint>

#define NEGV (-1e30f)

__device__ float g_diff[64];

__device__ __forceinline__ void cp_async16(uint32_t dst, const float* src) {
    asm volatile("cp.async.cg.shared.global [%0], [%1], 16;\n" :: "r"(dst), "l"(src));
}
__device__ __forceinline__ void cp_commit() { asm volatile("cp.async.commit_group;\n"); }
__device__ __forceinline__ void cp_wait2()  { asm volatile("cp.async.wait_group 2;\n"); }

__global__ __launch_bounds__(256, 1)
void crf_kernel(const float* __restrict__ logits,
                const int*   __restrict__ tags,
                const int*   __restrict__ mask,
                const float* __restrict__ trans,
                const float* __restrict__ start_tr,
                const float* __restrict__ end_tr,
                float* __restrict__ out)
{
    constexpr int S = 256, W = 32, T = 32;
    const int b   = blockIdx.x;
    const int tid = threadIdx.x;

    // Union: numerator pass (tags) and main loop (emit ring + etrans) are
    // temporally disjoint -> alias to stay under 48KB static smem.
    __shared__ __align__(16) union {
        struct { float emit[4][32 * 36]; float etrans[32 * 36]; } m; // 23040 B
        struct { int tags[256 * 33]; } n;                            // 33792 B
    } u;
    __shared__ float trans_s[32 * 33];
    __shared__ float Ms[32], Ss[32];
    __shared__ float warp_red[8];
    __shared__ int   ired[8];
    __shared__ float num_s;
    __shared__ int   len_s;

    // ---------------- sequence length (mask row sum) ----------------
    {
        int mv = mask[b * S + tid];                 // S == 256 == blockDim
        #pragma unroll
        for (int o = 16; o; o >>= 1) mv += __shfl_xor_sync(~0u, mv, o);
        if ((tid & 31) == 0) ired[tid >> 5] = mv;
        __syncthreads();
        if (tid == 0) {
            int l = 0;
            #pragma unroll
            for (int i = 0; i < 8; i++) l += ired[i];
            len_s = l;
        }
        __syncthreads();
    }
    const int len = len_s;

    // ---------------- numerator (joint likelihood) pass ----------------
    for (int i = tid; i < T * T; i += 256)
        trans_s[(i >> 5) * 33 + (i & 31)] = trans[i];
    for (int i = tid; i < S * W; i += 256)
        u.n.tags[(i >> 5) * 33 + (i & 31)] = tags[b * S * W + i];
    __syncthreads();

    const int warp = tid >> 5, lane = tid & 31;
    float acc = 0.f;
    for (int j = warp; j < S; j += 8) {
        const int d = lane;
        if (j < len && d <= j) {
            const int tg = u.n.tags[j * 33 + d];
            float sc = 0.f;
            if (tg != 0)
                sc += __ldg(&logits[(((size_t)b * S + j) * W + d) * T + tg]);
            if (d == j) {
                sc += start_tr[tg];
            } else {
                const int p = j - d - 1;
                float ts = 0.f;
                #pragma unroll 8
                for (int dd = 0; dd < W; dd++) {
                    const int ptg = u.n.tags[p * 33 + dd];
                    if (ptg != 0) ts += trans_s[ptg * 33 + tg];
                }
                sc += ts;
            }
            acc += sc;
        }
    }
    if (warp == 0) {                    // end-transition term
        const int tg = u.n.tags[(len - 1) * 33 + lane];
        if (tg != 0) acc += end_tr[tg];
    }
    #pragma unroll
    for (int o = 16; o; o >>= 1) acc += __shfl_xor_sync(~0u, acc, o);
    if (lane == 0) warp_red[warp] = acc;
    __syncthreads();
    if (tid == 0) {
        float sm = 0.f;
        #pragma unroll
        for (int i = 0; i < 8; i++) sm += warp_red[i];
        num_s = sm;
    }
    __syncthreads();   // tags region dead after this barrier

    // ---------------- denominator (forward scan) ----------------
    // exp(trans) with stride-36 rows: bank (4*t' + t) & 31 -> conflict free
    for (int i = tid; i < T * T; i += 256)
        u.m.etrans[(i >> 5) * 36 + (i & 31)] = __expf(trans[i]);

    const int t  = tid >> 3;        // output tag this thread serves
    const int s8 = tid & 7;         // 8-way split of the d/t' axis
    const float start_t = start_tr[t];
    const float* lb = logits + (size_t)b * S * W * T;

    // emit ring prefetch: thread copies 16B chunk `tid` of the 4KB tile
    const int crow = tid >> 3, ccol = tid & 7;
    const uint32_t emit_base  = (uint32_t)__cvta_generic_to_shared(u.m.emit);
    const uint32_t my_dst_off = (uint32_t)((crow * 36 + ccol * 4) * 4);
    #pragma unroll
    for (int pj = 0; pj < 3; pj++) {
        cp_async16(emit_base + (uint32_t)pj * 4608u + my_dst_off,
                   lb + pj * 1024 + tid * 4);
        cp_commit();
    }

    // I ring in registers: slot k lives at ring position s8 + 8k
    float I0 = 0.f, I1 = 0.f, I2 = 0.f, I3 = 0.f;
    const int sl0 = s8, sl1 = s8 + 8, sl2 = s8 + 16, sl3 = s8 + 24;
    const int c0 = 31 - sl0, c1 = 31 - sl1, c2 = 31 - sl2, c3 = 31 - sl3;

    for (int j = 0; j < len; j++) {
        cp_wait2();
        __syncthreads();
        const float* em = u.m.emit[j & 3];

        // ---- stage 1: alpha_j[t] as (M, S) pair ----
        const int d0 = (j + c0) & 31, d1 = (j + c1) & 31;
        const int d2 = (j + c2) & 31, d3 = (j + c3) & 31;
        const float e0 = em[d0 * 36 + t], e1 = em[d1 * 36 + t];
        const float e2 = em[d2 * 36 + t], e3 = em[d3 * 36 + t];
        float v0, v1, v2, v3;
        if (j >= 32) {
            v0 = e0 + I0; v1 = e1 + I1; v2 = e2 + I2; v3 = e3 + I3;
        } else {
            v0 = (sl0 < j) ? e0 + I0 : NEGV;
            v1 = (sl1 < j) ? e1 + I1 : NEGV;
            v2 = (sl2 < j) ? e2 + I2 : NEGV;
            v3 = (sl3 < j) ? e3 + I3 : ((sl3 == 31) ? e3 + start_t : NEGV);
        }
        float M = fmaxf(fmaxf(v0, v1), fmaxf(v2, v3));
        M = fmaxf(M, __shfl_xor_sync(~0u, M, 1));
        M = fmaxf(M, __shfl_xor_sync(~0u, M, 2));
        M = fmaxf(M, __shfl_xor_sync(~0u, M, 4));
        float Sv = __expf(v0 - M) + __expf(v1 - M)
                 + __expf(v2 - M) + __expf(v3 - M);
        Sv += __shfl_xor_sync(~0u, Sv, 1);
        Sv += __shfl_xor_sync(~0u, Sv, 2);
        Sv += __shfl_xor_sync(~0u, Sv, 4);
        if (s8 == 0) { Ms[t] = M; Ss[t] = Sv; }
        __syncthreads();

        // ---- stage 2: I_new[t] = logsumexp_{t'}(alpha[t'] + trans[t',t]) ----
        const float m0 = Ms[sl0], m1 = Ms[sl1], m2 = Ms[sl2], m3 = Ms[sl3];
        const float q0 = Ss[sl0], q1 = Ss[sl1], q2 = Ss[sl2], q3 = Ss[sl3];
        float mp = fmaxf(fmaxf(m0, m1), fmaxf(m2, m3));
        mp = fmaxf(mp, __shfl_xor_sync(~0u, mp, 1));
        mp = fmaxf(mp, __shfl_xor_sync(~0u, mp, 2));
        mp = fmaxf(mp, __shfl_xor_sync(~0u, mp, 4));
        float D = q0 * __expf(m0 - mp) * u.m.etrans[sl0 * 36 + t]
                + q1 * __expf(m1 - mp) * u.m.etrans[sl1 * 36 + t]
                + q2 * __expf(m2 - mp) * u.m.etrans[sl2 * 36 + t]
                + q3 * __expf(m3 - mp) * u.m.etrans[sl3 * 36 + t];
        D += __shfl_xor_sync(~0u, D, 1);
        D += __shfl_xor_sync(~0u, D, 2);
        D += __shfl_xor_sync(~0u, D, 4);
        if (s8 == (j & 7)) {            // owner of ring slot (j & 31)
            const float In = mp + __logf(D);
            const int kk = (j >> 3) & 3;
            if      (kk == 0) I0 = In;
            else if (kk == 1) I1 = In;
            else if (kk == 2) I2 = In;
            else              I3 = In;
        }

        if (j + 3 < S)
            cp_async16(emit_base + (uint32_t)((j + 3) & 3) * 4608u + my_dst_off,
                       lb + (size_t)(j + 3) * 1024 + tid * 4);
        cp_commit();
    }

    // ---------------- finalize ----------------
    __syncthreads();
    if (tid < 32) {
        float a = Ms[tid] + __logf(Ss[tid]) + end_tr[tid];
        float mm = a;
        #pragma unroll
        for (int o = 16; o; o >>= 1) mm = fmaxf(mm, __shfl_xor_sync(~0u, mm, o));
        float ssum = __expf(a - mm);
        #pragma unroll
        for (int o = 16; o; o >>= 1) ssum += __shfl_xor_sync(~0u, ssum, o);
        if (tid == 0) {
            const float den = mm + __logf(ssum);
            const float num = num_s;
            out[1 + b] = num;          // log_num output
            g_diff[b]  = num - den;
        }
    }
}

__global__ void finalize_kernel(float* __restrict__ out)
{
    float v = g_diff[threadIdx.x];
    #pragma unroll
    for (int o = 16; o; o >>= 1) v += __shfl_xor_sync(~0u, v, o);
    __shared__ float r[2];
    if ((threadIdx.x & 31) == 0) r[threadIdx.x >> 5] = v;
    __syncthreads();
    if (threadIdx.x == 0) out[0] = (r[0] + r[1]) * (1.f / 64.f);
}

extern "C" void kernel_launch(void* const* d_in, const int* in_sizes, int n_in,
                              void* d_out, int out_size)
{
    const float* logits  = (const float*)d_in[0];
    const int*   tags    = (const int*)d_in[1];
    const int*   mask    = (const int*)d_in[2];
    const float* trans   = (const float*)d_in[3];
    const float* st      = (const float*)d_in[4];
    const float* en      = (const float*)d_in[5];
    float*       out     = (float*)d_out;

    crf_kernel<<<64, 256>>>(logits, tags, mask, trans, st, en, out);
    finalize_kernel<<<1, 64>>>(out);
}

// round 2
// speedup vs baseline: 1.2613x; 1.2613x over previous
#include <cuda_runtime.h>
#include <cstdint>

#define NEGV (-1e30f)
#define L2E  1.4426950408889634f
#define LN2f 0.6931471805599453f

__device__ float g_diff[64];

static __device__ __forceinline__ float ex2f(float x){ float y; asm("ex2.approx.ftz.f32 %0, %1;" : "=f"(y) : "f"(x)); return y; }
static __device__ __forceinline__ float lg2f(float x){ float y; asm("lg2.approx.ftz.f32 %0, %1;" : "=f"(y) : "f"(x)); return y; }

__device__ __forceinline__ void cp_async16(uint32_t dst, const float* src){
    asm volatile("cp.async.cg.shared.global [%0], [%1], 16;\n" :: "r"(dst), "l"(src));
}
__device__ __forceinline__ void cp_commit(){ asm volatile("cp.async.commit_group;\n"); }
__device__ __forceinline__ void cp_wait2(){ asm volatile("cp.async.wait_group 2;\n"); }

struct ScanSmem {
    float emit[4][1024];     // 4-deep ring of 32x32 emit tiles (raw [d][t])
    float Iring[64 * 32];    // doubled 32-slot I ring, thread-private columns
};

// One scan step. Thread t = tag t; all state per-warp, no block sync.
template<bool MASKED>
__device__ __forceinline__ void scan_step(
    int j, int t, const float* __restrict__ lb,
    ScanSmem* sm, uint32_t emit_u32,
    const float (&E)[32], float start2,
    float& ref, float& w_keep, float& refb_keep)
{
    cp_wait2();
    __syncwarp();
    const float* em = sm->emit[j & 3] + t;
    const int base = ((j - 1) & 31) + 32;           // doubled-ring base row
    const float* ip = sm->Iring + (base - 31) * 32 + t;

    // stage 1: w[t] = sum_d exp2(emit[d,t]*L2E + I[d,t] - ref)
    float a0 = 0.f, a1 = 0.f, a2 = 0.f, a3 = 0.f;
    #pragma unroll
    for (int d = 0; d < 32; d++) {
        float ev = em[d * 32];
        float add;
        if (MASKED)
            add = (d < j) ? ip[(31 - d) * 32]
                          : ((d == j) ? start2 : NEGV);
        else
            add = ip[(31 - d) * 32];
        float e = ex2f(fmaf(ev, L2E, add) - ref);
        if      ((d & 3) == 0) a0 += e;
        else if ((d & 3) == 1) a1 += e;
        else if ((d & 3) == 2) a2 += e;
        else                   a3 += e;
    }
    float w = (a0 + a1) + (a2 + a3);                // == exp2(alpha[t] - ref)

    // stage 2: I_new[t] = ref + lg2( sum_t' w[t'] * exp(trans[t',t]) )
    float D0 = 0.f, D1 = 0.f, D2 = 0.f, D3 = 0.f;
    #pragma unroll
    for (int k = 0; k < 32; k++) {
        float wk = __shfl_sync(0xffffffffu, w, k);
        if      ((k & 3) == 0) D0 = fmaf(wk, E[k], D0);
        else if ((k & 3) == 1) D1 = fmaf(wk, E[k], D1);
        else if ((k & 3) == 2) D2 = fmaf(wk, E[k], D2);
        else                   D3 = fmaf(wk, E[k], D3);
    }
    // next-step normalization reference = max alpha (off critical path)
    float wm = w;
    #pragma unroll
    for (int o = 1; o < 32; o <<= 1)
        wm = fmaxf(wm, __shfl_xor_sync(0xffffffffu, wm, o));

    float Inew = ref + lg2f((D0 + D1) + (D2 + D3));
    const int r = j & 31;
    sm->Iring[r * 32 + t]        = Inew;
    sm->Iring[(r + 32) * 32 + t] = Inew;

    w_keep = w; refb_keep = ref;
    ref = ref + lg2f(wm);

    // prefetch emit tile j+3
    if (j + 3 < 256) {
        uint32_t dst = emit_u32 + (uint32_t)(((j + 3) & 3) * 4096) + (uint32_t)(t * 16);
        const float* src = lb + (j + 3) * 1024 + t * 4;
        #pragma unroll
        for (int i = 0; i < 8; i++) cp_async16(dst + i * 512u, src + i * 128);
    }
    cp_commit();
}

__global__ __launch_bounds__(256, 1)
void crf_kernel(const float* __restrict__ logits,
                const int*   __restrict__ tags,
                const int*   __restrict__ mask,
                const float* __restrict__ trans,
                const float* __restrict__ start_tr,
                const float* __restrict__ end_tr,
                float* __restrict__ out)
{
    constexpr int S = 256, W = 32, T = 32;
    const int b   = blockIdx.x;
    const int tid = threadIdx.x;

    __shared__ __align__(16) union SU {
        ScanSmem m;                 // 24576 B (scan phase)
        int tags[256 * 33];         // 33792 B (numerator phase)
    } u;
    __shared__ float trans_s[32 * 33];
    __shared__ float warp_red[8];
    __shared__ int   ired[8];
    __shared__ float num_s;
    __shared__ int   len_s;

    // ---------------- sequence length ----------------
    {
        int mv = mask[b * S + tid];
        #pragma unroll
        for (int o = 16; o; o >>= 1) mv += __shfl_xor_sync(~0u, mv, o);
        if ((tid & 31) == 0) ired[tid >> 5] = mv;
        __syncthreads();
        if (tid == 0) {
            int l = 0;
            #pragma unroll
            for (int i = 0; i < 8; i++) l += ired[i];
            len_s = l;
        }
        __syncthreads();
    }
    const int len = len_s;

    // ---------------- numerator pass (all 8 warps) ----------------
    for (int i = tid; i < T * T; i += 256)
        trans_s[(i >> 5) * 33 + (i & 31)] = trans[i];
    for (int i = tid; i < S * W; i += 256)
        u.tags[(i >> 5) * 33 + (i & 31)] = tags[b * S * W + i];
    __syncthreads();

    const int warp = tid >> 5, lane = tid & 31;
    float acc = 0.f;
    for (int j = warp; j < S; j += 8) {
        const int d = lane;
        if (j < len && d <= j) {
            const int tg = u.tags[j * 33 + d];
            float sc = 0.f;
            if (tg != 0)
                sc += __ldg(&logits[(((size_t)b * S + j) * W + d) * T + tg]);
            if (d == j) {
                sc += start_tr[tg];
            } else {
                const int p = j - d - 1;
                float ts = 0.f;
                #pragma unroll 8
                for (int dd = 0; dd < W; dd++) {
                    const int ptg = u.tags[p * 33 + dd];
                    if (ptg != 0) ts += trans_s[ptg * 33 + tg];
                }
                sc += ts;
            }
            acc += sc;
        }
    }
    if (warp == 0) {
        const int tg = u.tags[(len - 1) * 33 + lane];
        if (tg != 0) acc += end_tr[tg];
    }
    #pragma unroll
    for (int o = 16; o; o >>= 1) acc += __shfl_xor_sync(~0u, acc, o);
    if (lane == 0) warp_red[warp] = acc;
    __syncthreads();
    if (tid == 0) {
        float sm = 0.f;
        #pragma unroll
        for (int i = 0; i < 8; i++) sm += warp_red[i];
        num_s = sm;
    }
    __syncthreads();    // tags region dead; warps 1..7 done

    if (tid >= 32) return;

    // ---------------- denominator scan (warp 0 only) ----------------
    const int t = tid;
    float E[32];
    #pragma unroll
    for (int k = 0; k < 32; k++)
        E[k] = ex2f(trans_s[k * 33 + t] * L2E);     // exp(trans[k][t])
    const float start2 = start_tr[t] * L2E;
    const float end2   = end_tr[t]   * L2E;
    const float* lb = logits + (size_t)b * S * W * T;

    const uint32_t emit_u32 = (uint32_t)__cvta_generic_to_shared(&u.m.emit[0][0]);
    #pragma unroll
    for (int pj = 0; pj < 3; pj++) {
        uint32_t dst = emit_u32 + (uint32_t)(pj * 4096) + (uint32_t)(t * 16);
        const float* src = lb + pj * 1024 + t * 4;
        #pragma unroll
        for (int i = 0; i < 8; i++) cp_async16(dst + i * 512u, src + i * 128);
        cp_commit();
    }

    float ref = 0.f, w_keep = 1.f, refb_keep = 0.f;

    const int pl = (len < 32) ? len : 32;
    for (int j = 0; j < pl; j++)
        scan_step<true>(j, t, lb, &u.m, emit_u32, E, start2, ref, w_keep, refb_keep);
    for (int j = 32; j < len; j++)
        scan_step<false>(j, t, lb, &u.m, emit_u32, E, start2, ref, w_keep, refb_keep);

    // ---------------- finalize ----------------
    const float alphaF = refb_keep + lg2f(w_keep);  // alpha_{len-1}[t] in log2
    float v = alphaF + end2;
    float m = v;
    #pragma unroll
    for (int o = 1; o < 32; o <<= 1)
        m = fmaxf(m, __shfl_xor_sync(0xffffffffu, m, o));
    float s = ex2f(v - m);
    #pragma unroll
    for (int o = 1; o < 32; o <<= 1)
        s += __shfl_xor_sync(0xffffffffu, s, o);
    if (t == 0) {
        const float den = LN2f * (m + lg2f(s));
        const float num = num_s;
        out[1 + b] = num;
        g_diff[b]  = num - den;
    }
}

__global__ void finalize_kernel(float* __restrict__ out)
{
    float v = g_diff[threadIdx.x];
    #pragma unroll
    for (int o = 16; o; o >>= 1) v += __shfl_xor_sync(~0u, v, o);
    __shared__ float r[2];
    if ((threadIdx.x & 31) == 0) r[threadIdx.x >> 5] = v;
    __syncthreads();
    if (threadIdx.x == 0) out[0] = (r[0] + r[1]) * (1.f / 64.f);
}

extern "C" void kernel_launch(void* const* d_in, const int* in_sizes, int n_in,
                              void* d_out, int out_size)
{
    const float* logits = (const float*)d_in[0];
    const int*   tags   = (const int*)d_in[1];
    const int*   mask   = (const int*)d_in[2];
    const float* trans  = (const float*)d_in[3];
    const float* st     = (const float*)d_in[4];
    const float* en     = (const float*)d_in[5];
    float*       out    = (float*)d_out;

    crf_kernel<<<64, 256>>>(logits, tags, mask, trans, st, en, out);
    finalize_kernel<<<1, 64>>>(out);
}

// round 3
// speedup vs baseline: 1.2619x; 1.0005x over previous
#include <cuda_runtime.h>
#include <cstdint>

#define NEGV (-1e30f)
#define L2E  1.4426950408889634f
#define LN2f 0.6931471805599453f

__device__ float g_diff[64];

static __device__ __forceinline__ float ex2f(float x){ float y; asm("ex2.approx.ftz.f32 %0, %1;" : "=f"(y) : "f"(x)); return y; }
static __device__ __forceinline__ float lg2f(float x){ float y; asm("lg2.approx.ftz.f32 %0, %1;" : "=f"(y) : "f"(x)); return y; }

__device__ __forceinline__ void cp_async16(uint32_t dst, const float* src){
    asm volatile("cp.async.cg.shared.global [%0], [%1], 16;\n" :: "r"(dst), "l"(src));
}
__device__ __forceinline__ void cp_commit(){ asm volatile("cp.async.commit_group;\n"); }
__device__ __forceinline__ void cp_wait2(){ asm volatile("cp.async.wait_group 2;\n"); }

struct ScanSmem {
    float emit[4][1024];     // 4-deep ring of 32x32 emit tiles (raw [d][t])
    float Iring[64 * 32];    // doubled 32-slot I ring, thread-private columns
};

// One scan step. Thread t = tag t; all state per-warp, no block sync.
template<bool MASKED>
__device__ __forceinline__ void scan_step(
    int j, int t, const float* __restrict__ lb,
    ScanSmem* sm, uint32_t emit_u32,
    const float (&E)[32], float start2,
    float& ref, float& w_keep, float& refb_keep)
{
    cp_wait2();
    __syncwarp();
    const float* em = sm->emit[j & 3] + t;
    const int base = ((j - 1) & 31) + 32;           // doubled-ring base row
    const float* ip = sm->Iring + (base - 31) * 32 + t;

    // stage 1: w[t] = sum_d exp2(emit[d,t]*L2E + I[d,t] - ref)
    float a0 = 0.f, a1 = 0.f, a2 = 0.f, a3 = 0.f;
    #pragma unroll
    for (int d = 0; d < 32; d++) {
        float ev = em[d * 32];
        float add;
        if (MASKED)
            add = (d < j) ? ip[(31 - d) * 32]
                          : ((d == j) ? start2 : NEGV);
        else
            add = ip[(31 - d) * 32];
        float e = ex2f(fmaf(ev, L2E, add) - ref);
        if      ((d & 3) == 0) a0 += e;
        else if ((d & 3) == 1) a1 += e;
        else if ((d & 3) == 2) a2 += e;
        else                   a3 += e;
    }
    float w = (a0 + a1) + (a2 + a3);                // == exp2(alpha[t] - ref)

    // stage 2: I_new[t] = ref + lg2( sum_t' w[t'] * exp(trans[t',t]) )
    float D0 = 0.f, D1 = 0.f, D2 = 0.f, D3 = 0.f;
    #pragma unroll
    for (int k = 0; k < 32; k++) {
        float wk = __shfl_sync(0xffffffffu, w, k);
        if      ((k & 3) == 0) D0 = fmaf(wk, E[k], D0);
        else if ((k & 3) == 1) D1 = fmaf(wk, E[k], D1);
        else if ((k & 3) == 2) D2 = fmaf(wk, E[k], D2);
        else                   D3 = fmaf(wk, E[k], D3);
    }
    // next-step normalization reference = max alpha (off critical path)
    float wm = w;
    #pragma unroll
    for (int o = 1; o < 32; o <<= 1)
        wm = fmaxf(wm, __shfl_xor_sync(0xffffffffu, wm, o));

    float Inew = ref + lg2f((D0 + D1) + (D2 + D3));
    const int r = j & 31;
    sm->Iring[r * 32 + t]        = Inew;
    sm->Iring[(r + 32) * 32 + t] = Inew;

    w_keep = w; refb_keep = ref;
    ref = ref + lg2f(wm);

    // prefetch emit tile j+3
    if (j + 3 < 256) {
        uint32_t dst = emit_u32 + (uint32_t)(((j + 3) & 3) * 4096) + (uint32_t)(t * 16);
        const float* src = lb + (j + 3) * 1024 + t * 4;
        #pragma unroll
        for (int i = 0; i < 8; i++) cp_async16(dst + i * 512u, src + i * 128);
    }
    cp_commit();
}

__global__ __launch_bounds__(256, 1)
void crf_kernel(const float* __restrict__ logits,
                const int*   __restrict__ tags,
                const int*   __restrict__ mask,
                const float* __restrict__ trans,
                const float* __restrict__ start_tr,
                const float* __restrict__ end_tr,
                float* __restrict__ out)
{
    constexpr int S = 256, W = 32, T = 32;
    const int b   = blockIdx.x;
    const int tid = threadIdx.x;

    __shared__ __align__(16) union SU {
        ScanSmem m;                 // 24576 B (scan phase)
        int tags[256 * 33];         // 33792 B (numerator phase)
    } u;
    __shared__ float trans_s[32 * 33];
    __shared__ float warp_red[8];
    __shared__ int   ired[8];
    __shared__ float num_s;
    __shared__ int   len_s;

    // ---------------- sequence length ----------------
    {
        int mv = mask[b * S + tid];
        #pragma unroll
        for (int o = 16; o; o >>= 1) mv += __shfl_xor_sync(~0u, mv, o);
        if ((tid & 31) == 0) ired[tid >> 5] = mv;
        __syncthreads();
        if (tid == 0) {
            int l = 0;
            #pragma unroll
            for (int i = 0; i < 8; i++) l += ired[i];
            len_s = l;
        }
        __syncthreads();
    }
    const int len = len_s;

    // ---------------- numerator pass (all 8 warps) ----------------
    for (int i = tid; i < T * T; i += 256)
        trans_s[(i >> 5) * 33 + (i & 31)] = trans[i];
    for (int i = tid; i < S * W; i += 256)
        u.tags[(i >> 5) * 33 + (i & 31)] = tags[b * S * W + i];
    __syncthreads();

    const int warp = tid >> 5, lane = tid & 31;
    float acc = 0.f;
    for (int j = warp; j < S; j += 8) {
        const int d = lane;
        if (j < len && d <= j) {
            const int tg = u.tags[j * 33 + d];
            float sc = 0.f;
            if (tg != 0)
                sc += __ldg(&logits[(((size_t)b * S + j) * W + d) * T + tg]);
            if (d == j) {
                sc += start_tr[tg];
            } else {
                const int p = j - d - 1;
                float ts = 0.f;
                #pragma unroll 8
                for (int dd = 0; dd < W; dd++) {
                    const int ptg = u.tags[p * 33 + dd];
                    if (ptg != 0) ts += trans_s[ptg * 33 + tg];
                }
                sc += ts;
            }
            acc += sc;
        }
    }
    if (warp == 0) {
        const int tg = u.tags[(len - 1) * 33 + lane];
        if (tg != 0) acc += end_tr[tg];
    }
    #pragma unroll
    for (int o = 16; o; o >>= 1) acc += __shfl_xor_sync(~0u, acc, o);
    if (lane == 0) warp_red[warp] = acc;
    __syncthreads();
    if (tid == 0) {
        float sm = 0.f;
        #pragma unroll
        for (int i = 0; i < 8; i++) sm += warp_red[i];
        num_s = sm;
    }
    __syncthreads();    // tags region dead; warps 1..7 done

    if (tid >= 32) return;

    // ---------------- denominator scan (warp 0 only) ----------------
    const int t = tid;
    float E[32];
    #pragma unroll
    for (int k = 0; k < 32; k++)
        E[k] = ex2f(trans_s[k * 33 + t] * L2E);     // exp(trans[k][t])
    const float start2 = start_tr[t] * L2E;
    const float end2   = end_tr[t]   * L2E;
    const float* lb = logits + (size_t)b * S * W * T;

    const uint32_t emit_u32 = (uint32_t)__cvta_generic_to_shared(&u.m.emit[0][0]);
    #pragma unroll
    for (int pj = 0; pj < 3; pj++) {
        uint32_t dst = emit_u32 + (uint32_t)(pj * 4096) + (uint32_t)(t * 16);
        const float* src = lb + pj * 1024 + t * 4;
        #pragma unroll
        for (int i = 0; i < 8; i++) cp_async16(dst + i * 512u, src + i * 128);
        cp_commit();
    }

    float ref = 0.f, w_keep = 1.f, refb_keep = 0.f;

    const int pl = (len < 32) ? len : 32;
    for (int j = 0; j < pl; j++)
        scan_step<true>(j, t, lb, &u.m, emit_u32, E, start2, ref, w_keep, refb_keep);
    for (int j = 32; j < len; j++)
        scan_step<false>(j, t, lb, &u.m, emit_u32, E, start2, ref, w_keep, refb_keep);

    // ---------------- finalize ----------------
    const float alphaF = refb_keep + lg2f(w_keep);  // alpha_{len-1}[t] in log2
    float v = alphaF + end2;
    float m = v;
    #pragma unroll
    for (int o = 1; o < 32; o <<= 1)
        m = fmaxf(m, __shfl_xor_sync(0xffffffffu, m, o));
    float s = ex2f(v - m);
    #pragma unroll
    for (int o = 1; o < 32; o <<= 1)
        s += __shfl_xor_sync(0xffffffffu, s, o);
    if (t == 0) {
        const float den = LN2f * (m + lg2f(s));
        const float num = num_s;
        out[1 + b] = num;
        g_diff[b]  = num - den;
    }
}

__global__ void finalize_kernel(float* __restrict__ out)
{
    float v = g_diff[threadIdx.x];
    #pragma unroll
    for (int o = 16; o; o >>= 1) v += __shfl_xor_sync(~0u, v, o);
    __shared__ float r[2];
    if ((threadIdx.x & 31) == 0) r[threadIdx.x >> 5] = v;
    __syncthreads();
    if (threadIdx.x == 0) out[0] = (r[0] + r[1]) * (1.f / 64.f);
}

extern "C" void kernel_launch(void* const* d_in, const int* in_sizes, int n_in,
                              void* d_out, int out_size)
{
    const float* logits = (const float*)d_in[0];
    const int*   tags   = (const int*)d_in[1];
    const int*   mask   = (const int*)d_in[2];
    const float* trans  = (const float*)d_in[3];
    const float* st     = (const float*)d_in[4];
    const float* en     = (const float*)d_in[5];
    float*       out    = (float*)d_out;

    crf_kernel<<<64, 256>>>(logits, tags, mask, trans, st, en, out);
    finalize_kernel<<<1, 64>>>(out);
}